// round 14
// baseline (speedup 1.0000x reference)
#include <cuda_runtime.h>
#include <cuda_fp16.h>
#include <math.h>
#include <stdint.h>

#define BATCH 4
#define HRES  64
#define WRES  128
#define CDIM  768
#define HEADS 8
#define HDIM  96
#define WIN   8
#define NTOK  64
#define MTOK  32768
#define HID   3072

#define WQ_OFF  0
#define WP_OFF  1769472
#define WF1_OFF 2359296
#define WF2_OFF 7077888
#define WTOT    9437184

// ---------------- scratch ----------------
__device__ float g_qkv[(size_t)MTOK * 2304];
__device__ float g_proj[(size_t)MTOK * CDIM];
__device__ float g_xmid[(size_t)MTOK * CDIM];
__device__ float g_x2[(size_t)MTOK * CDIM];
__device__ float g_h2[(size_t)MTOK * CDIM];
__device__ float g_rpb[HEADS * NTOK * NTOK];
__device__ float g_scale[HEADS];
__device__ float g_qkvbias[2304];
// fp16 operand buffers: A-side 2-limb (hi/lo), weights 1-limb
__device__ __half g_xhi[(size_t)MTOK * CDIM],  g_xlo[(size_t)MTOK * CDIM];
__device__ __half g_aohi[(size_t)MTOK * CDIM], g_aolo[(size_t)MTOK * CDIM];
__device__ __half g_xmhi[(size_t)MTOK * CDIM], g_xmlo[(size_t)MTOK * CDIM];
__device__ __half g_gahi[(size_t)MTOK * HID],  g_galo[(size_t)MTOK * HID];
__device__ __half g_wh[WTOT];

// windowed row m -> image token index, applying roll by +shift
__device__ __forceinline__ int win2img(int m, int shift) {
    int w = m >> 6, tok = m & 63;
    int b = w >> 7, wi = w & 127;
    int y  = (((wi >> 4) << 3) + (tok >> 3) + shift) & 63;
    int xx = (((wi & 15) << 3) + (tok & 7) + shift) & 127;
    return (b << 13) + (y << 7) + xx;
}

__device__ __forceinline__ uint32_t smem_u32(const void* p) {
    uint32_t a;
    asm("{ .reg .u64 t; cvta.to.shared.u64 t, %1; cvt.u32.u64 %0, t; }" : "=r"(a) : "l"(p));
    return a;
}

__device__ __forceinline__ void split_f16(float v, unsigned short& h, unsigned short& l) {
    __half hh = __float2half_rn(v);
    h = __half_as_ushort(hh);
    l = __half_as_ushort(__float2half_rn(v - __half2float(hh)));
}

// ---------------- mma.sync / ldmatrix / cp.async helpers ----------------
__device__ __forceinline__ void mma_f16(float* c, const uint32_t* a, const uint32_t* b) {
    asm volatile(
        "mma.sync.aligned.m16n8k16.row.col.f32.f16.f16.f32 "
        "{%0,%1,%2,%3}, {%4,%5,%6,%7}, {%8,%9}, {%0,%1,%2,%3};"
        : "+f"(c[0]), "+f"(c[1]), "+f"(c[2]), "+f"(c[3])
        : "r"(a[0]), "r"(a[1]), "r"(a[2]), "r"(a[3]), "r"(b[0]), "r"(b[1]));
}
__device__ __forceinline__ void ldsm4(uint32_t* r, uint32_t addr) {
    asm volatile("ldmatrix.sync.aligned.m8n8.x4.shared.b16 {%0,%1,%2,%3}, [%4];"
                 : "=r"(r[0]), "=r"(r[1]), "=r"(r[2]), "=r"(r[3]) : "r"(addr));
}
#define CPA16(dst, src) asm volatile("cp.async.cg.shared.global [%0], [%1], 16;" :: "r"(dst), "l"(src) : "memory")
#define CPCOMMIT()      asm volatile("cp.async.commit_group;" ::: "memory")
#define CPWAIT1()       asm volatile("cp.async.wait_group 1;" ::: "memory")

// ---------------- fp32 -> fp16 hi/lo (A-side) ----------------
__global__ void cvt_kernel(const float* __restrict__ src, __half* __restrict__ hi,
                           __half* __restrict__ lo, int n4) {
    int i = blockIdx.x * 256 + threadIdx.x;
    if (i >= n4) return;
    float4 v = ((const float4*)src)[i];
    ushort4 h, l;
    split_f16(v.x, h.x, l.x);
    split_f16(v.y, h.y, l.y);
    split_f16(v.z, h.z, l.z);
    split_f16(v.w, h.w, l.w);
    ((ushort4*)hi)[i] = h;
    ((ushort4*)lo)[i] = l;
}

// ---------------- fp32 -> fp16 (weights, single limb) ----------------
__global__ void cvtw_kernel(const float* __restrict__ src, __half* __restrict__ hi, int n4) {
    int i = blockIdx.x * 256 + threadIdx.x;
    if (i >= n4) return;
    float4 v = ((const float4*)src)[i];
    ushort4 h;
    h.x = __half_as_ushort(__float2half_rn(v.x));
    h.y = __half_as_ushort(__float2half_rn(v.y));
    h.z = __half_as_ushort(__float2half_rn(v.z));
    h.w = __half_as_ushort(__float2half_rn(v.w));
    ((ushort4*)hi)[i] = h;
}

// ---------------- HMMA GEMM: C[m][n] = sum_k A[m][k]*W[n][k] + bias ----------------
// CTA tile 128(M) x 256(N), BK=32, 3-stage cp.async ring, 1 CTA/SM (255 regs x 8 warps).
// 256 threads: 8 warps as 2m x 4n, warp tile 64x64.
// fp16 2-limb A x 1-limb B: D = (Ah+Al)*Bh  (2 MMAs per micro-tile).
// Prefetch of chunk c+2 issues BEFORE chunk c's MMAs (stage (c+2)%3 was last read in
// chunk c-1; the top-of-iteration barrier proves all warps are done with it).
// One __syncthreads per chunk. wait_group 1 => chunk c's group complete at top of iter c.
// mode 0: fp32 bias epilogue, 256 out cols/CTA
// mode 1: fc1 gated-GELU, gate/val interleaved -> 128 out cols/CTA, fp16 hi/lo out
// smem per stage (112B padded rows): Ahi@0 (14336) Alo@14336 B@28672 (256x112) ; stage=57344
#define STG 57344
#define SMEM_MMA (3 * STG)

__global__ __launch_bounds__(256, 1)
void gemm_mma(const __half* __restrict__ Ahi, const __half* __restrict__ Alo,
              const __half* __restrict__ Bh,
              const float* __restrict__ bias, float* __restrict__ Cout,
              __half* __restrict__ Chi, __half* __restrict__ Clo,
              int K, int Nout, int mode, int gatherShift) {
    extern __shared__ char sm[];
    uint32_t smb = smem_u32(sm);
    int tid = threadIdx.x, wid = tid >> 5, lane = tid & 31;
    int nB = blockIdx.x, mB = blockIdx.y;

    // ---- cp.async coordinates: A 2 tasks (x2 limbs), B 4 tasks ----
    ptrdiff_t dA = Alo - Ahi;
    const __half* aSrc[2]; uint32_t aDst[2];
    #pragma unroll
    for (int i = 0; i < 2; i++) {
        int idx = tid + 256 * i, row = idx >> 2, ch = idx & 3;
        int m = mB * 128 + row;
        int rg = (gatherShift >= 0) ? win2img(m, gatherShift) : m;
        aSrc[i] = Ahi + (size_t)rg * K + ch * 8;
        aDst[i] = smb + row * 112 + ch * 16;
    }
    const __half* bSrc[4]; uint32_t bDst[4];
    #pragma unroll
    for (int i = 0; i < 4; i++) {
        int idx = tid + 256 * i, j = idx >> 2, ch = idx & 3;
        int grow = mode ? (nB * 128 + (j >> 1) + (j & 1) * HID) : (nB * 256 + j);
        bSrc[i] = Bh + (size_t)grow * K + ch * 8;
        bDst[i] = smb + 28672 + j * 112 + ch * 16;
    }

    #define PREFETCH(s, c) do {                                              \
        uint32_t so = (uint32_t)(s) * STG;                                   \
        _Pragma("unroll")                                                    \
        for (int i = 0; i < 2; i++) {                                        \
            const __half* sh = aSrc[i] + (c) * 32;                           \
            CPA16(aDst[i] + so, sh);                                         \
            CPA16(aDst[i] + so + 14336, sh + dA);                            \
        }                                                                    \
        _Pragma("unroll")                                                    \
        for (int i = 0; i < 4; i++) {                                        \
            CPA16(bDst[i] + so, bSrc[i] + (c) * 32);                         \
        }                                                                    \
    } while (0)

    // ---- per-warp/lane compute coordinates (2m x 4n warps, warp tile 64x64) ----
    int m0 = (wid & 1) * 64, n0 = (wid >> 1) * 64;
    uint32_t aoff = ((lane & 7) + ((lane >> 3) & 1) * 8) * 112 + ((lane >> 4) & 1) * 16;
    uint32_t boff = ((lane & 7) + ((lane >> 4) & 1) * 8) * 112 + ((lane >> 3) & 1) * 16;

    float acc[4][8][4];
    #pragma unroll
    for (int mt = 0; mt < 4; mt++)
        #pragma unroll
        for (int nt = 0; nt < 8; nt++)
            #pragma unroll
            for (int e = 0; e < 4; e++) acc[mt][nt][e] = 0.0f;

    int nchunk = K >> 5;
    PREFETCH(0, 0); CPCOMMIT();
    PREFETCH(1, 1); CPCOMMIT();

    for (int c = 0; c < nchunk; c++) {
        CPWAIT1();            // newest group = chunk c+1's -> chunk c complete
        __syncthreads();      // publish chunk c; all warps done reading chunk c-1
        if (c + 2 < nchunk) PREFETCH((c + 2) % 3, c + 2);
        CPCOMMIT();
        uint32_t sa = smb + (uint32_t)(c % 3) * STG;
        uint32_t sb = sa + 28672;
        #pragma unroll
        for (int kk = 0; kk < 2; kk++) {
            uint32_t bh[4][4];
            #pragma unroll
            for (int bt = 0; bt < 4; bt++) {
                uint32_t bd = sb + (n0 + bt * 16) * 112 + kk * 32 + boff;
                ldsm4(bh[bt], bd);
            }
            #pragma unroll
            for (int mt = 0; mt < 4; mt++) {
                uint32_t ah[4], al[4];
                uint32_t ad = sa + (m0 + mt * 16) * 112 + kk * 32 + aoff;
                ldsm4(ah, ad);
                ldsm4(al, ad + 14336);
                #pragma unroll
                for (int nt = 0; nt < 8; nt++) {
                    float* cc = acc[mt][nt];
                    const uint32_t* bp = &bh[nt >> 1][(nt & 1) * 2];
                    mma_f16(cc, ah, bp);
                    mma_f16(cc, al, bp);
                }
            }
        }
    }

    // ---- epilogue (registers only; no smem hazard) ----
    int g = lane >> 2, t = lane & 3;
    int rowBase = mB * 128 + m0;
    if (mode == 0) {
        int colBase = nB * 256 + n0;
        #pragma unroll
        for (int mt = 0; mt < 4; mt++)
            #pragma unroll
            for (int nt = 0; nt < 8; nt++) {
                float* a = acc[mt][nt];
                int row = rowBase + mt * 16 + g;
                int col = colBase + nt * 8 + 2 * t;
                float b0 = bias[col], b1 = bias[col + 1];
                float2 v0 = {a[0] + b0, a[1] + b1};
                float2 v1 = {a[2] + b0, a[3] + b1};
                *(float2*)&Cout[(size_t)row * Nout + col] = v0;
                *(float2*)&Cout[(size_t)(row + 8) * Nout + col] = v1;
            }
    } else {
        #pragma unroll
        for (int mt = 0; mt < 4; mt++)
            #pragma unroll
            for (int nt = 0; nt < 8; nt++) {
                float* a = acc[mt][nt];
                int row = rowBase + mt * 16 + g;
                int col = nB * 128 + ((n0 + nt * 8) >> 1) + t;
                float bg = bias[col], bv = bias[HID + col];
                float gt0 = a[0] + bg, vl0 = a[1] + bv;
                float gt1 = a[2] + bg, vl1 = a[3] + bv;
                float o0 = 0.5f * gt0 * (1.0f + erff(gt0 * 0.7071067811865475f)) * vl0;
                float o1 = 0.5f * gt1 * (1.0f + erff(gt1 * 0.7071067811865475f)) * vl1;
                unsigned short h0, l0, h1, l1;
                split_f16(o0, h0, l0);
                split_f16(o1, h1, l1);
                size_t i0 = (size_t)row * Nout + col;
                size_t i1 = (size_t)(row + 8) * Nout + col;
                Chi[i0] = __ushort_as_half(h0); Clo[i0] = __ushort_as_half(l0);
                Chi[i1] = __ushort_as_half(h1); Clo[i1] = __ushort_as_half(l1);
            }
    }
    #undef PREFETCH
}

// ---------------- CPB MLP + rpb table + scales + qkv bias ----------------
__device__ __forceinline__ float coordf(int i) {
    float t = (float)(i - 7) * (8.0f / 7.0f);
    return copysignf(log2f(fabsf(t) + 1.0f) * (1.0f / 3.0f), t);
}

__global__ void cpb_kernel(int d, const float* __restrict__ qb, const float* __restrict__ vb,
                           const float* __restrict__ ls, const float* __restrict__ w1,
                           const float* __restrict__ b1, const float* __restrict__ w2) {
    __shared__ float tbl[225][8];
    int tid = threadIdx.x;
    if (tid < 225) {
        int i = tid / 15, j = tid % 15;
        float c0 = coordf(i), c1 = coordf(j);
        float o[8] = {0,0,0,0,0,0,0,0};
        const float* W1 = w1 + d * 1024;
        const float* B1 = b1 + d * 512;
        const float* W2 = w2 + d * 4096;
        for (int u = 0; u < 512; u++) {
            float hv = fmaxf(c0 * W1[u*2] + c1 * W1[u*2+1] + B1[u], 0.0f);
            #pragma unroll
            for (int hh = 0; hh < 8; hh++) o[hh] += hv * W2[hh*512 + u];
        }
        #pragma unroll
        for (int hh = 0; hh < 8; hh++) tbl[tid][hh] = o[hh];
    }
    if (tid < 8) g_scale[tid] = __expf(fminf(ls[d*8 + tid], 4.605170185988091f));
    for (int n = tid; n < 2304; n += 256) {
        float bb = 0.0f;
        if (n < 768) bb = qb[d*768 + n];
        else if (n >= 1536) bb = vb[d*768 + n - 1536];
        g_qkvbias[n] = bb;
    }
    __syncthreads();
    for (int idx = tid; idx < HEADS*NTOK*NTOK; idx += 256) {
        int h = idx >> 12, rem = idx & 4095;
        int i = rem >> 6, j = rem & 63;
        int dy = (i >> 3) - (j >> 3) + 7;
        int dx = (i & 7) - (j & 7) + 7;
        float t = tbl[dy*15 + dx][h];
        g_rpb[idx] = 16.0f / (1.0f + __expf(-t));
    }
}

// ---------------- attention: one CTA per (window, head) ----------------
#define QS_LD 97
#define AT_LD 65
#define ATTN_SMEM ((3 * 64 * QS_LD + 64 * AT_LD) * (int)sizeof(float))

__global__ __launch_bounds__(256)
void attn_kernel(int shift) {
    extern __shared__ float smf[];
    float* Qs = smf;
    float* Ks = Qs + 64 * QS_LD;
    float* Vs = Ks + 64 * QS_LD;
    float* At = Vs + 64 * QS_LD;
    int wh = blockIdx.x;
    int w = wh >> 3, h = wh & 7;
    int tid = threadIdx.x;

    #pragma unroll
    for (int s = 0; s < 3; s++) {
        float* dst = (s == 0) ? Qs : ((s == 1) ? Ks : Vs);
        for (int idx = tid; idx < 64 * 24; idx += 256) {
            int row = idx / 24, c4 = idx % 24;
            float4 v = *(const float4*)&g_qkv[(size_t)(w * 64 + row) * 2304 + s * 768 + h * 96 + c4 * 4];
            float* p = dst + row * QS_LD + c4 * 4;
            p[0] = v.x; p[1] = v.y; p[2] = v.z; p[3] = v.w;
        }
    }
    __syncthreads();

    if (tid < 128) {
        int r = tid & 63;
        float* rowp = (tid < 64) ? (Qs + r * QS_LD) : (Ks + r * QS_LD);
        float ss = 0.0f;
        #pragma unroll 8
        for (int c = 0; c < 96; c++) ss += rowp[c] * rowp[c];
        float f = 1.0f / fmaxf(sqrtf(ss), 1e-12f);
        if (tid < 64) f *= g_scale[h];
        #pragma unroll 8
        for (int c = 0; c < 96; c++) rowp[c] *= f;
    }
    __syncthreads();

    int ty = tid >> 4, tx = tid & 15;
    int i0 = ty * 4, j0 = tx * 4;
    float acc[4][4];
    #pragma unroll
    for (int r = 0; r < 4; r++)
        #pragma unroll
        for (int c = 0; c < 4; c++) acc[r][c] = 0.0f;
    for (int dd = 0; dd < 96; dd++) {
        float q[4], k[4];
        #pragma unroll
        for (int r = 0; r < 4; r++) q[r] = Qs[(i0 + r) * QS_LD + dd];
        #pragma unroll
        for (int c = 0; c < 4; c++) k[c] = Ks[(j0 + c) * QS_LD + dd];
        #pragma unroll
        for (int r = 0; r < 4; r++)
            #pragma unroll
            for (int c = 0; c < 4; c++) acc[r][c] += q[r] * k[c];
    }
    int wi = w & 127;
    int wy = wi >> 4, wx = wi & 15;
    #pragma unroll
    for (int r = 0; r < 4; r++) {
        #pragma unroll
        for (int c = 0; c < 4; c++) {
            int i = i0 + r, j = j0 + c;
            float aval = acc[r][c] + g_rpb[h * 4096 + i * 64 + j];
            if (shift > 0) {
                int yi = wy * 8 + (i >> 3), xi = wx * 8 + (i & 7);
                int yj = wy * 8 + (j >> 3), xj = wx * 8 + (j & 7);
                int ri = (yi >= 60 ? 2 : (yi >= 56 ? 1 : 0)) * 3 + (xi >= 124 ? 2 : (xi >= 120 ? 1 : 0));
                int rj = (yj >= 60 ? 2 : (yj >= 56 ? 1 : 0)) * 3 + (xj >= 124 ? 2 : (xj >= 120 ? 1 : 0));
                if (ri != rj) aval -= 100.0f;
            }
            At[i * AT_LD + j] = aval;
        }
    }
    __syncthreads();

    {
        int r = tid >> 2, qd = tid & 3;
        int jb = qd * 16;
        float mx = -1e30f;
        #pragma unroll
        for (int j = 0; j < 16; j++) mx = fmaxf(mx, At[r * AT_LD + jb + j]);
        mx = fmaxf(mx, __shfl_xor_sync(0xffffffffu, mx, 1));
        mx = fmaxf(mx, __shfl_xor_sync(0xffffffffu, mx, 2));
        float s = 0.0f;
        #pragma unroll
        for (int j = 0; j < 16; j++) {
            float e = __expf(At[r * AT_LD + jb + j] - mx);
            At[r * AT_LD + jb + j] = e;
            s += e;
        }
        s += __shfl_xor_sync(0xffffffffu, s, 1);
        s += __shfl_xor_sync(0xffffffffu, s, 2);
        float inv = 1.0f / s;
        #pragma unroll
        for (int j = 0; j < 16; j++) At[r * AT_LD + jb + j] *= inv;
    }
    __syncthreads();

    int d0 = tx * 6;
    float o[4][6];
    #pragma unroll
    for (int r = 0; r < 4; r++)
        #pragma unroll
        for (int c = 0; c < 6; c++) o[r][c] = 0.0f;
    for (int j = 0; j < 64; j++) {
        float a[4], vv[6];
        #pragma unroll
        for (int r = 0; r < 4; r++) a[r] = At[(i0 + r) * AT_LD + j];
        #pragma unroll
        for (int c = 0; c < 6; c++) vv[c] = Vs[j * QS_LD + d0 + c];
        #pragma unroll
        for (int r = 0; r < 4; r++)
            #pragma unroll
            for (int c = 0; c < 6; c++) o[r][c] += a[r] * vv[c];
    }
    #pragma unroll
    for (int r = 0; r < 4; r++)
        #pragma unroll
        for (int c = 0; c < 6; c++) {
            size_t idx = (size_t)(w * 64 + i0 + r) * 768 + h * 96 + d0 + c;
            unsigned short hh, ll;
            split_f16(o[r][c], hh, ll);
            g_aohi[idx] = __ushort_as_half(hh);
            g_aolo[idx] = __ushort_as_half(ll);
        }
}

// ---------------- LayerNorm + residual (+ optional fp16 hi/lo emit) ----------------
__global__ void ln_kernel(const float* __restrict__ src, const float* __restrict__ resid,
                          const float* __restrict__ gamma, const float* __restrict__ beta,
                          float* __restrict__ outp,
                          __half* __restrict__ ohi, __half* __restrict__ olo,
                          int scatterShift) {
    int warp = threadIdx.x >> 5, lane = threadIdx.x & 31;
    int m = blockIdx.x * 8 + warp;
    const float* sp = src + (size_t)m * 768;
    float v[24];
    #pragma unroll
    for (int i = 0; i < 24; i++) v[i] = sp[i * 32 + lane];
    float s = 0.0f;
    #pragma unroll
    for (int i = 0; i < 24; i++) s += v[i];
    #pragma unroll
    for (int o = 16; o; o >>= 1) s += __shfl_xor_sync(0xffffffffu, s, o);
    float mu = s * (1.0f / 768.0f);
    float q = 0.0f;
    #pragma unroll
    for (int i = 0; i < 24; i++) { float dd = v[i] - mu; q += dd * dd; }
    #pragma unroll
    for (int o = 16; o; o >>= 1) q += __shfl_xor_sync(0xffffffffu, q, o);
    float rs = rsqrtf(q * (1.0f / 768.0f) + 1e-5f);
    int timg = (scatterShift >= 0) ? win2img(m, scatterShift) : m;
    size_t ob = (size_t)timg * 768;
    #pragma unroll
    for (int i = 0; i < 24; i++) {
        int c = i * 32 + lane;
        float ov = resid[ob + c] + (v[i] - mu) * rs * gamma[c] + beta[c];
        outp[ob + c] = ov;
        if (ohi != nullptr) {
            unsigned short hh, ll;
            split_f16(ov, hh, ll);
            ohi[ob + c] = __ushort_as_half(hh);
            olo[ob + c] = __ushort_as_half(ll);
        }
    }
}

// ---------------- driver ----------------
extern "C" void kernel_launch(void* const* d_in, const int* in_sizes, int n_in,
                              void* d_out, int out_size) {
    const float* x     = (const float*)d_in[0];
    const float* n1g   = (const float*)d_in[1];
    const float* n1b   = (const float*)d_in[2];
    const float* n2g   = (const float*)d_in[3];
    const float* n2b   = (const float*)d_in[4];
    const float* qkvw  = (const float*)d_in[5];
    const float* qb    = (const float*)d_in[6];
    const float* vb    = (const float*)d_in[7];
    const float* ls    = (const float*)d_in[8];
    const float* w1    = (const float*)d_in[9];
    const float* b1    = (const float*)d_in[10];
    const float* w2    = (const float*)d_in[11];
    const float* projw = (const float*)d_in[12];
    const float* projb = (const float*)d_in[13];
    const float* fc1w  = (const float*)d_in[14];
    const float* fc1b  = (const float*)d_in[15];
    const float* fc2w  = (const float*)d_in[16];
    const float* fc2b  = (const float*)d_in[17];
    float* out = (float*)d_out;

    float *p_qkv, *p_proj, *p_xmid, *p_x2, *p_h2, *p_qkvbias;
    __half *p_xhi, *p_xlo, *p_aohi, *p_aolo, *p_xmhi, *p_xmlo, *p_gahi, *p_galo, *p_wh;
    cudaGetSymbolAddress((void**)&p_qkv, g_qkv);
    cudaGetSymbolAddress((void**)&p_proj, g_proj);
    cudaGetSymbolAddress((void**)&p_xmid, g_xmid);
    cudaGetSymbolAddress((void**)&p_x2, g_x2);
    cudaGetSymbolAddress((void**)&p_h2, g_h2);
    cudaGetSymbolAddress((void**)&p_qkvbias, g_qkvbias);
    cudaGetSymbolAddress((void**)&p_xhi, g_xhi);
    cudaGetSymbolAddress((void**)&p_xlo, g_xlo);
    cudaGetSymbolAddress((void**)&p_aohi, g_aohi);
    cudaGetSymbolAddress((void**)&p_aolo, g_aolo);
    cudaGetSymbolAddress((void**)&p_xmhi, g_xmhi);
    cudaGetSymbolAddress((void**)&p_xmlo, g_xmlo);
    cudaGetSymbolAddress((void**)&p_gahi, g_gahi);
    cudaGetSymbolAddress((void**)&p_galo, g_galo);
    cudaGetSymbolAddress((void**)&p_wh, g_wh);

    cudaFuncSetAttribute(attn_kernel, cudaFuncAttributeMaxDynamicSharedMemorySize, ATTN_SMEM);
    cudaFuncSetAttribute(gemm_mma, cudaFuncAttributeMaxDynamicSharedMemorySize, SMEM_MMA);

    for (int d = 0; d < 2; d++) {
        int shift = d ? 4 : 0;
        const float* xin = d ? p_x2 : x;

        cpb_kernel<<<1, 256>>>(d, qb, vb, ls, w1, b1, w2);

        if (d == 0)
            cvt_kernel<<<(MTOK * CDIM / 4 + 255) / 256, 256>>>(x, p_xhi, p_xlo, MTOK * CDIM / 4);
        cvtw_kernel<<<(2304*768/4 + 255) / 256, 256>>>(qkvw + (size_t)d * 2304 * 768,
                                                       p_wh + WQ_OFF, 2304*768/4);

        // QKV (fused roll+window gather on A): M=32768, N=2304, K=768
        gemm_mma<<<dim3(9, MTOK / 128), 256, SMEM_MMA>>>(
            p_xhi, p_xlo, p_wh + WQ_OFF,
            p_qkvbias, p_qkv, nullptr, nullptr, 768, 2304, 0, shift);

        // weight conversions for later GEMMs (deferred past the QKV launch)
        cvtw_kernel<<<(768*768/4 + 255) / 256, 256>>>(projw + (size_t)d * 768 * 768,
                                                      p_wh + WP_OFF, 768*768/4);
        cvtw_kernel<<<(6144*768/4 + 255) / 256, 256>>>(fc1w + (size_t)d * 6144 * 768,
                                                       p_wh + WF1_OFF, 6144*768/4);
        cvtw_kernel<<<(768*3072/4 + 255) / 256, 256>>>(fc2w + (size_t)d * 768 * 3072,
                                                       p_wh + WF2_OFF, 768*3072/4);

        attn_kernel<<<512 * HEADS, 256, ATTN_SMEM>>>(shift);

        // proj: N=768, K=768
        gemm_mma<<<dim3(3, MTOK / 128), 256, SMEM_MMA>>>(
            p_aohi, p_aolo, p_wh + WP_OFF,
            projb + d * 768, p_proj, nullptr, nullptr, 768, 768, 0, -1);

        // x_mid = shortcut + LN(proj), un-window + un-roll scatter, emit fp16 hi/lo
        ln_kernel<<<MTOK / 8, 256>>>(p_proj, xin, n1g + d * 768, n1b + d * 768,
                                     p_xmid, p_xmhi, p_xmlo, shift);

        // FC1 gated-GELU: out cols 3072 (128/CTA), K=768, emits fp16 hi/lo
        gemm_mma<<<dim3(24, MTOK / 128), 256, SMEM_MMA>>>(
            p_xmhi, p_xmlo, p_wh + WF1_OFF,
            fc1b + (size_t)d * 2 * HID, nullptr, p_gahi, p_galo, 768, HID, 1, -1);

        // FC2: N=768, K=3072
        gemm_mma<<<dim3(3, MTOK / 128), 256, SMEM_MMA>>>(
            p_gahi, p_galo, p_wh + WF2_OFF,
            fc2b + d * 768, p_h2, nullptr, nullptr, 3072, 768, 0, -1);

        // final LN: block 0 -> x2 (+fp16 hi/lo reused as next layer's QKV A), block 1 -> out
        ln_kernel<<<MTOK / 8, 256>>>(p_h2, p_xmid, n2g + d * 768, n2b + d * 768,
                                     d == 0 ? p_x2 : out,
                                     d == 0 ? p_xhi : nullptr,
                                     d == 0 ? p_xlo : nullptr, -1);
    }
    (void)in_sizes; (void)n_in; (void)out_size;
}

// round 15
// speedup vs baseline: 1.2873x; 1.2873x over previous
#include <cuda_runtime.h>
#include <cuda_fp16.h>
#include <math.h>
#include <stdint.h>

#define BATCH 4
#define HRES  64
#define WRES  128
#define CDIM  768
#define HEADS 8
#define HDIM  96
#define WIN   8
#define NTOK  64
#define MTOK  32768
#define HID   3072

#define WQ_OFF  0
#define WP_OFF  1769472
#define WF1_OFF 2359296
#define WF2_OFF 7077888
#define WTOT    9437184

// ---------------- scratch ----------------
__device__ float g_qkv[(size_t)MTOK * 2304];
__device__ float g_proj[(size_t)MTOK * CDIM];
__device__ float g_xmid[(size_t)MTOK * CDIM];
__device__ float g_x2[(size_t)MTOK * CDIM];
__device__ float g_h2[(size_t)MTOK * CDIM];
__device__ float g_rpb[HEADS * NTOK * NTOK];
__device__ float g_scale[HEADS];
__device__ float g_qkvbias[2304];
// fp16 operand buffers: A-side 2-limb (hi/lo), weights 1-limb
__device__ __half g_xhi[(size_t)MTOK * CDIM],  g_xlo[(size_t)MTOK * CDIM];
__device__ __half g_aohi[(size_t)MTOK * CDIM], g_aolo[(size_t)MTOK * CDIM];
__device__ __half g_xmhi[(size_t)MTOK * CDIM], g_xmlo[(size_t)MTOK * CDIM];
__device__ __half g_gahi[(size_t)MTOK * HID],  g_galo[(size_t)MTOK * HID];
__device__ __half g_wh[WTOT];

// windowed row m -> image token index, applying roll by +shift
__device__ __forceinline__ int win2img(int m, int shift) {
    int w = m >> 6, tok = m & 63;
    int b = w >> 7, wi = w & 127;
    int y  = (((wi >> 4) << 3) + (tok >> 3) + shift) & 63;
    int xx = (((wi & 15) << 3) + (tok & 7) + shift) & 127;
    return (b << 13) + (y << 7) + xx;
}

__device__ __forceinline__ uint32_t smem_u32(const void* p) {
    uint32_t a;
    asm("{ .reg .u64 t; cvta.to.shared.u64 t, %1; cvt.u32.u64 %0, t; }" : "=r"(a) : "l"(p));
    return a;
}

__device__ __forceinline__ void split_f16(float v, unsigned short& h, unsigned short& l) {
    __half hh = __float2half_rn(v);
    h = __half_as_ushort(hh);
    l = __half_as_ushort(__float2half_rn(v - __half2float(hh)));
}

// ---------------- mma.sync / ldmatrix / cp.async helpers ----------------
__device__ __forceinline__ void mma_f16(float* c, const uint32_t* a, const uint32_t* b) {
    asm volatile(
        "mma.sync.aligned.m16n8k16.row.col.f32.f16.f16.f32 "
        "{%0,%1,%2,%3}, {%4,%5,%6,%7}, {%8,%9}, {%0,%1,%2,%3};"
        : "+f"(c[0]), "+f"(c[1]), "+f"(c[2]), "+f"(c[3])
        : "r"(a[0]), "r"(a[1]), "r"(a[2]), "r"(a[3]), "r"(b[0]), "r"(b[1]));
}
__device__ __forceinline__ void ldsm4(uint32_t* r, uint32_t addr) {
    asm volatile("ldmatrix.sync.aligned.m8n8.x4.shared.b16 {%0,%1,%2,%3}, [%4];"
                 : "=r"(r[0]), "=r"(r[1]), "=r"(r[2]), "=r"(r[3]) : "r"(addr));
}
#define CPA16(dst, src) asm volatile("cp.async.cg.shared.global [%0], [%1], 16;" :: "r"(dst), "l"(src) : "memory")
#define CPCOMMIT()      asm volatile("cp.async.commit_group;" ::: "memory")
#define CPWAIT1()       asm volatile("cp.async.wait_group 1;" ::: "memory")

// ---------------- fp32 -> fp16 hi/lo (A-side) ----------------
__global__ void cvt_kernel(const float* __restrict__ src, __half* __restrict__ hi,
                           __half* __restrict__ lo, int n4) {
    int i = blockIdx.x * 256 + threadIdx.x;
    if (i >= n4) return;
    float4 v = ((const float4*)src)[i];
    ushort4 h, l;
    split_f16(v.x, h.x, l.x);
    split_f16(v.y, h.y, l.y);
    split_f16(v.z, h.z, l.z);
    split_f16(v.w, h.w, l.w);
    ((ushort4*)hi)[i] = h;
    ((ushort4*)lo)[i] = l;
}

// ---------------- fp32 -> fp16 (weights, single limb) ----------------
__global__ void cvtw_kernel(const float* __restrict__ src, __half* __restrict__ hi, int n4) {
    int i = blockIdx.x * 256 + threadIdx.x;
    if (i >= n4) return;
    float4 v = ((const float4*)src)[i];
    ushort4 h;
    h.x = __half_as_ushort(__float2half_rn(v.x));
    h.y = __half_as_ushort(__float2half_rn(v.y));
    h.z = __half_as_ushort(__float2half_rn(v.z));
    h.w = __half_as_ushort(__float2half_rn(v.w));
    ((ushort4*)hi)[i] = h;
}

// ---------------- HMMA GEMM: C[m][n] = sum_k A[m][k]*W[n][k] + bias ----------------
// PROVEN R12 CONFIG: CTA tile 128(M) x 128(N), BK=32, 2 stages, 2 CTAs/SM.
// 128 threads: 4 warps 2m x 2n, warp tile 64x64. Inter-CTA overlap hides the
// two per-chunk barriers (1-CTA/SM variant measured 29% slower).
// fp16 2-limb A x 1-limb B: D = (Ah+Al)*Bh  (2 MMAs per micro-tile).
// mode 0: fp32 bias epilogue, 128 out cols/CTA
// mode 1: fc1 gated-GELU, gate/val interleaved -> 64 out cols/CTA, fp16 hi/lo out
// smem per stage (112B padded rows): Ahi@0 Alo@14336 Bh@28672 ; stage=43008
#define STG 43008
#define SMEM_MMA (2 * STG)

__global__ __launch_bounds__(128, 2)
void gemm_mma(const __half* __restrict__ Ahi, const __half* __restrict__ Alo,
              const __half* __restrict__ Bh,
              const float* __restrict__ bias, float* __restrict__ Cout,
              __half* __restrict__ Chi, __half* __restrict__ Clo,
              int K, int Nout, int mode, int gatherShift) {
    extern __shared__ char sm[];
    uint32_t smb = smem_u32(sm);
    int tid = threadIdx.x, wid = tid >> 5, lane = tid & 31;
    int nB = blockIdx.x, mB = blockIdx.y;

    // ---- cp.async coordinates: A 4 tasks (x2 limbs), B 4 tasks ----
    ptrdiff_t dA = Alo - Ahi;
    const __half* aSrc[4]; uint32_t aDst[4];
    #pragma unroll
    for (int i = 0; i < 4; i++) {
        int idx = tid + 128 * i, row = idx >> 2, ch = idx & 3;
        int m = mB * 128 + row;
        int rg = (gatherShift >= 0) ? win2img(m, gatherShift) : m;
        aSrc[i] = Ahi + (size_t)rg * K + ch * 8;
        aDst[i] = smb + row * 112 + ch * 16;
    }
    const __half* bSrc[4]; uint32_t bDst[4];
    #pragma unroll
    for (int i = 0; i < 4; i++) {
        int idx = tid + 128 * i, j = idx >> 2, ch = idx & 3;
        int grow = mode ? (nB * 64 + (j >> 1) + (j & 1) * HID) : (nB * 128 + j);
        bSrc[i] = Bh + (size_t)grow * K + ch * 8;
        bDst[i] = smb + 28672 + j * 112 + ch * 16;
    }

    #define PREFETCH(s, c) do {                                              \
        uint32_t so = (uint32_t)(s) * STG;                                   \
        _Pragma("unroll")                                                    \
        for (int i = 0; i < 4; i++) {                                        \
            const __half* sh = aSrc[i] + (c) * 32;                           \
            CPA16(aDst[i] + so, sh);                                         \
            CPA16(aDst[i] + so + 14336, sh + dA);                            \
        }                                                                    \
        _Pragma("unroll")                                                    \
        for (int i = 0; i < 4; i++) {                                        \
            CPA16(bDst[i] + so, bSrc[i] + (c) * 32);                         \
        }                                                                    \
    } while (0)

    // ---- per-warp/lane compute coordinates (2m x 2n warps, warp tile 64x64) ----
    int m0 = (wid & 1) * 64, n0 = (wid >> 1) * 64;
    uint32_t aoff = ((lane & 7) + ((lane >> 3) & 1) * 8) * 112 + ((lane >> 4) & 1) * 16;
    uint32_t boff = ((lane & 7) + ((lane >> 4) & 1) * 8) * 112 + ((lane >> 3) & 1) * 16;

    float acc[4][8][4];
    #pragma unroll
    for (int mt = 0; mt < 4; mt++)
        #pragma unroll
        for (int nt = 0; nt < 8; nt++)
            #pragma unroll
            for (int e = 0; e < 4; e++) acc[mt][nt][e] = 0.0f;

    int nchunk = K >> 5;
    PREFETCH(0, 0); CPCOMMIT();
    PREFETCH(1, 1); CPCOMMIT();

    for (int c = 0; c < nchunk; c++) {
        CPWAIT1();
        __syncthreads();
        int s = c & 1;
        uint32_t sa = smb + s * STG;
        uint32_t sb = sa + 28672;
        #pragma unroll
        for (int kk = 0; kk < 2; kk++) {
            uint32_t bh[4][4];
            #pragma unroll
            for (int bt = 0; bt < 4; bt++) {
                uint32_t bd = sb + (n0 + bt * 16) * 112 + kk * 32 + boff;
                ldsm4(bh[bt], bd);
            }
            #pragma unroll
            for (int mt = 0; mt < 4; mt++) {
                uint32_t ah[4], al[4];
                uint32_t ad = sa + (m0 + mt * 16) * 112 + kk * 32 + aoff;
                ldsm4(ah, ad);
                ldsm4(al, ad + 14336);
                #pragma unroll
                for (int nt = 0; nt < 8; nt++) {
                    float* cc = acc[mt][nt];
                    const uint32_t* bp = &bh[nt >> 1][(nt & 1) * 2];
                    mma_f16(cc, ah, bp);
                    mma_f16(cc, al, bp);
                }
            }
        }
        __syncthreads();
        if (c + 2 < nchunk) PREFETCH(s, c + 2);
        CPCOMMIT();
    }

    // ---- epilogue ----
    int g = lane >> 2, t = lane & 3;
    int rowBase = mB * 128 + m0;
    if (mode == 0) {
        int colBase = nB * 128 + n0;
        #pragma unroll
        for (int mt = 0; mt < 4; mt++)
            #pragma unroll
            for (int nt = 0; nt < 8; nt++) {
                float* a = acc[mt][nt];
                int row = rowBase + mt * 16 + g;
                int col = colBase + nt * 8 + 2 * t;
                float b0 = bias[col], b1 = bias[col + 1];
                float2 v0 = {a[0] + b0, a[1] + b1};
                float2 v1 = {a[2] + b0, a[3] + b1};
                *(float2*)&Cout[(size_t)row * Nout + col] = v0;
                *(float2*)&Cout[(size_t)(row + 8) * Nout + col] = v1;
            }
    } else {
        #pragma unroll
        for (int mt = 0; mt < 4; mt++)
            #pragma unroll
            for (int nt = 0; nt < 8; nt++) {
                float* a = acc[mt][nt];
                int row = rowBase + mt * 16 + g;
                int col = nB * 64 + ((n0 + nt * 8) >> 1) + t;
                float bg = bias[col], bv = bias[HID + col];
                float gt0 = a[0] + bg, vl0 = a[1] + bv;
                float gt1 = a[2] + bg, vl1 = a[3] + bv;
                float o0 = 0.5f * gt0 * (1.0f + erff(gt0 * 0.7071067811865475f)) * vl0;
                float o1 = 0.5f * gt1 * (1.0f + erff(gt1 * 0.7071067811865475f)) * vl1;
                unsigned short h0, l0, h1, l1;
                split_f16(o0, h0, l0);
                split_f16(o1, h1, l1);
                size_t i0 = (size_t)row * Nout + col;
                size_t i1 = (size_t)(row + 8) * Nout + col;
                Chi[i0] = __ushort_as_half(h0); Clo[i0] = __ushort_as_half(l0);
                Chi[i1] = __ushort_as_half(h1); Clo[i1] = __ushort_as_half(l1);
            }
    }
    #undef PREFETCH
}

// ---------------- CPB MLP + rpb table + scales + qkv bias ----------------
__device__ __forceinline__ float coordf(int i) {
    float t = (float)(i - 7) * (8.0f / 7.0f);
    return copysignf(log2f(fabsf(t) + 1.0f) * (1.0f / 3.0f), t);
}

__global__ void cpb_kernel(int d, const float* __restrict__ qb, const float* __restrict__ vb,
                           const float* __restrict__ ls, const float* __restrict__ w1,
                           const float* __restrict__ b1, const float* __restrict__ w2) {
    __shared__ float tbl[225][8];
    int tid = threadIdx.x;
    if (tid < 225) {
        int i = tid / 15, j = tid % 15;
        float c0 = coordf(i), c1 = coordf(j);
        float o[8] = {0,0,0,0,0,0,0,0};
        const float* W1 = w1 + d * 1024;
        const float* B1 = b1 + d * 512;
        const float* W2 = w2 + d * 4096;
        for (int u = 0; u < 512; u++) {
            float hv = fmaxf(c0 * W1[u*2] + c1 * W1[u*2+1] + B1[u], 0.0f);
            #pragma unroll
            for (int hh = 0; hh < 8; hh++) o[hh] += hv * W2[hh*512 + u];
        }
        #pragma unroll
        for (int hh = 0; hh < 8; hh++) tbl[tid][hh] = o[hh];
    }
    if (tid < 8) g_scale[tid] = __expf(fminf(ls[d*8 + tid], 4.605170185988091f));
    for (int n = tid; n < 2304; n += 256) {
        float bb = 0.0f;
        if (n < 768) bb = qb[d*768 + n];
        else if (n >= 1536) bb = vb[d*768 + n - 1536];
        g_qkvbias[n] = bb;
    }
    __syncthreads();
    for (int idx = tid; idx < HEADS*NTOK*NTOK; idx += 256) {
        int h = idx >> 12, rem = idx & 4095;
        int i = rem >> 6, j = rem & 63;
        int dy = (i >> 3) - (j >> 3) + 7;
        int dx = (i & 7) - (j & 7) + 7;
        float t = tbl[dy*15 + dx][h];
        g_rpb[idx] = 16.0f / (1.0f + __expf(-t));
    }
}

// ---------------- attention: one CTA per (window, head) ----------------
#define QS_LD 97
#define AT_LD 65
#define ATTN_SMEM ((3 * 64 * QS_LD + 64 * AT_LD) * (int)sizeof(float))

__global__ __launch_bounds__(256)
void attn_kernel(int shift) {
    extern __shared__ float smf[];
    float* Qs = smf;
    float* Ks = Qs + 64 * QS_LD;
    float* Vs = Ks + 64 * QS_LD;
    float* At = Vs + 64 * QS_LD;
    int wh = blockIdx.x;
    int w = wh >> 3, h = wh & 7;
    int tid = threadIdx.x;

    #pragma unroll
    for (int s = 0; s < 3; s++) {
        float* dst = (s == 0) ? Qs : ((s == 1) ? Ks : Vs);
        for (int idx = tid; idx < 64 * 24; idx += 256) {
            int row = idx / 24, c4 = idx % 24;
            float4 v = *(const float4*)&g_qkv[(size_t)(w * 64 + row) * 2304 + s * 768 + h * 96 + c4 * 4];
            float* p = dst + row * QS_LD + c4 * 4;
            p[0] = v.x; p[1] = v.y; p[2] = v.z; p[3] = v.w;
        }
    }
    __syncthreads();

    if (tid < 128) {
        int r = tid & 63;
        float* rowp = (tid < 64) ? (Qs + r * QS_LD) : (Ks + r * QS_LD);
        float ss = 0.0f;
        #pragma unroll 8
        for (int c = 0; c < 96; c++) ss += rowp[c] * rowp[c];
        float f = 1.0f / fmaxf(sqrtf(ss), 1e-12f);
        if (tid < 64) f *= g_scale[h];
        #pragma unroll 8
        for (int c = 0; c < 96; c++) rowp[c] *= f;
    }
    __syncthreads();

    int ty = tid >> 4, tx = tid & 15;
    int i0 = ty * 4, j0 = tx * 4;
    float acc[4][4];
    #pragma unroll
    for (int r = 0; r < 4; r++)
        #pragma unroll
        for (int c = 0; c < 4; c++) acc[r][c] = 0.0f;
    for (int dd = 0; dd < 96; dd++) {
        float q[4], k[4];
        #pragma unroll
        for (int r = 0; r < 4; r++) q[r] = Qs[(i0 + r) * QS_LD + dd];
        #pragma unroll
        for (int c = 0; c < 4; c++) k[c] = Ks[(j0 + c) * QS_LD + dd];
        #pragma unroll
        for (int r = 0; r < 4; r++)
            #pragma unroll
            for (int c = 0; c < 4; c++) acc[r][c] += q[r] * k[c];
    }
    int wi = w & 127;
    int wy = wi >> 4, wx = wi & 15;
    #pragma unroll
    for (int r = 0; r < 4; r++) {
        #pragma unroll
        for (int c = 0; c < 4; c++) {
            int i = i0 + r, j = j0 + c;
            float aval = acc[r][c] + g_rpb[h * 4096 + i * 64 + j];
            if (shift > 0) {
                int yi = wy * 8 + (i >> 3), xi = wx * 8 + (i & 7);
                int yj = wy * 8 + (j >> 3), xj = wx * 8 + (j & 7);
                int ri = (yi >= 60 ? 2 : (yi >= 56 ? 1 : 0)) * 3 + (xi >= 124 ? 2 : (xi >= 120 ? 1 : 0));
                int rj = (yj >= 60 ? 2 : (yj >= 56 ? 1 : 0)) * 3 + (xj >= 124 ? 2 : (xj >= 120 ? 1 : 0));
                if (ri != rj) aval -= 100.0f;
            }
            At[i * AT_LD + j] = aval;
        }
    }
    __syncthreads();

    {
        int r = tid >> 2, qd = tid & 3;
        int jb = qd * 16;
        float mx = -1e30f;
        #pragma unroll
        for (int j = 0; j < 16; j++) mx = fmaxf(mx, At[r * AT_LD + jb + j]);
        mx = fmaxf(mx, __shfl_xor_sync(0xffffffffu, mx, 1));
        mx = fmaxf(mx, __shfl_xor_sync(0xffffffffu, mx, 2));
        float s = 0.0f;
        #pragma unroll
        for (int j = 0; j < 16; j++) {
            float e = __expf(At[r * AT_LD + jb + j] - mx);
            At[r * AT_LD + jb + j] = e;
            s += e;
        }
        s += __shfl_xor_sync(0xffffffffu, s, 1);
        s += __shfl_xor_sync(0xffffffffu, s, 2);
        float inv = 1.0f / s;
        #pragma unroll
        for (int j = 0; j < 16; j++) At[r * AT_LD + jb + j] *= inv;
    }
    __syncthreads();

    int d0 = tx * 6;
    float o[4][6];
    #pragma unroll
    for (int r = 0; r < 4; r++)
        #pragma unroll
        for (int c = 0; c < 6; c++) o[r][c] = 0.0f;
    for (int j = 0; j < 64; j++) {
        float a[4], vv[6];
        #pragma unroll
        for (int r = 0; r < 4; r++) a[r] = At[(i0 + r) * AT_LD + j];
        #pragma unroll
        for (int c = 0; c < 6; c++) vv[c] = Vs[j * QS_LD + d0 + c];
        #pragma unroll
        for (int r = 0; r < 4; r++)
            #pragma unroll
            for (int c = 0; c < 6; c++) o[r][c] += a[r] * vv[c];
    }
    #pragma unroll
    for (int r = 0; r < 4; r++)
        #pragma unroll
        for (int c = 0; c < 6; c++) {
            size_t idx = (size_t)(w * 64 + i0 + r) * 768 + h * 96 + d0 + c;
            unsigned short hh, ll;
            split_f16(o[r][c], hh, ll);
            g_aohi[idx] = __ushort_as_half(hh);
            g_aolo[idx] = __ushort_as_half(ll);
        }
}

// ---------------- LayerNorm + residual (+ optional fp16 hi/lo emit) ----------------
__global__ void ln_kernel(const float* __restrict__ src, const float* __restrict__ resid,
                          const float* __restrict__ gamma, const float* __restrict__ beta,
                          float* __restrict__ outp,
                          __half* __restrict__ ohi, __half* __restrict__ olo,
                          int scatterShift) {
    int warp = threadIdx.x >> 5, lane = threadIdx.x & 31;
    int m = blockIdx.x * 8 + warp;
    const float* sp = src + (size_t)m * 768;
    float v[24];
    #pragma unroll
    for (int i = 0; i < 24; i++) v[i] = sp[i * 32 + lane];
    float s = 0.0f;
    #pragma unroll
    for (int i = 0; i < 24; i++) s += v[i];
    #pragma unroll
    for (int o = 16; o; o >>= 1) s += __shfl_xor_sync(0xffffffffu, s, o);
    float mu = s * (1.0f / 768.0f);
    float q = 0.0f;
    #pragma unroll
    for (int i = 0; i < 24; i++) { float dd = v[i] - mu; q += dd * dd; }
    #pragma unroll
    for (int o = 16; o; o >>= 1) q += __shfl_xor_sync(0xffffffffu, q, o);
    float rs = rsqrtf(q * (1.0f / 768.0f) + 1e-5f);
    int timg = (scatterShift >= 0) ? win2img(m, scatterShift) : m;
    size_t ob = (size_t)timg * 768;
    #pragma unroll
    for (int i = 0; i < 24; i++) {
        int c = i * 32 + lane;
        float ov = resid[ob + c] + (v[i] - mu) * rs * gamma[c] + beta[c];
        outp[ob + c] = ov;
        if (ohi != nullptr) {
            unsigned short hh, ll;
            split_f16(ov, hh, ll);
            ohi[ob + c] = __ushort_as_half(hh);
            olo[ob + c] = __ushort_as_half(ll);
        }
    }
}

// ---------------- driver ----------------
extern "C" void kernel_launch(void* const* d_in, const int* in_sizes, int n_in,
                              void* d_out, int out_size) {
    const float* x     = (const float*)d_in[0];
    const float* n1g   = (const float*)d_in[1];
    const float* n1b   = (const float*)d_in[2];
    const float* n2g   = (const float*)d_in[3];
    const float* n2b   = (const float*)d_in[4];
    const float* qkvw  = (const float*)d_in[5];
    const float* qb    = (const float*)d_in[6];
    const float* vb    = (const float*)d_in[7];
    const float* ls    = (const float*)d_in[8];
    const float* w1    = (const float*)d_in[9];
    const float* b1    = (const float*)d_in[10];
    const float* w2    = (const float*)d_in[11];
    const float* projw = (const float*)d_in[12];
    const float* projb = (const float*)d_in[13];
    const float* fc1w  = (const float*)d_in[14];
    const float* fc1b  = (const float*)d_in[15];
    const float* fc2w  = (const float*)d_in[16];
    const float* fc2b  = (const float*)d_in[17];
    float* out = (float*)d_out;

    float *p_qkv, *p_proj, *p_xmid, *p_x2, *p_h2, *p_qkvbias;
    __half *p_xhi, *p_xlo, *p_aohi, *p_aolo, *p_xmhi, *p_xmlo, *p_gahi, *p_galo, *p_wh;
    cudaGetSymbolAddress((void**)&p_qkv, g_qkv);
    cudaGetSymbolAddress((void**)&p_proj, g_proj);
    cudaGetSymbolAddress((void**)&p_xmid, g_xmid);
    cudaGetSymbolAddress((void**)&p_x2, g_x2);
    cudaGetSymbolAddress((void**)&p_h2, g_h2);
    cudaGetSymbolAddress((void**)&p_qkvbias, g_qkvbias);
    cudaGetSymbolAddress((void**)&p_xhi, g_xhi);
    cudaGetSymbolAddress((void**)&p_xlo, g_xlo);
    cudaGetSymbolAddress((void**)&p_aohi, g_aohi);
    cudaGetSymbolAddress((void**)&p_aolo, g_aolo);
    cudaGetSymbolAddress((void**)&p_xmhi, g_xmhi);
    cudaGetSymbolAddress((void**)&p_xmlo, g_xmlo);
    cudaGetSymbolAddress((void**)&p_gahi, g_gahi);
    cudaGetSymbolAddress((void**)&p_galo, g_galo);
    cudaGetSymbolAddress((void**)&p_wh, g_wh);

    cudaFuncSetAttribute(attn_kernel, cudaFuncAttributeMaxDynamicSharedMemorySize, ATTN_SMEM);
    cudaFuncSetAttribute(gemm_mma, cudaFuncAttributeMaxDynamicSharedMemorySize, SMEM_MMA);

    for (int d = 0; d < 2; d++) {
        int shift = d ? 4 : 0;
        const float* xin = d ? p_x2 : x;

        cpb_kernel<<<1, 256>>>(d, qb, vb, ls, w1, b1, w2);

        if (d == 0)
            cvt_kernel<<<(MTOK * CDIM / 4 + 255) / 256, 256>>>(x, p_xhi, p_xlo, MTOK * CDIM / 4);
        cvtw_kernel<<<(2304*768/4 + 255) / 256, 256>>>(qkvw + (size_t)d * 2304 * 768,
                                                       p_wh + WQ_OFF, 2304*768/4);

        // QKV (fused roll+window gather on A): M=32768, N=2304, K=768
        gemm_mma<<<dim3(18, MTOK / 128), 128, SMEM_MMA>>>(
            p_xhi, p_xlo, p_wh + WQ_OFF,
            p_qkvbias, p_qkv, nullptr, nullptr, 768, 2304, 0, shift);

        // weight conversions for later GEMMs (deferred past the QKV launch)
        cvtw_kernel<<<(768*768/4 + 255) / 256, 256>>>(projw + (size_t)d * 768 * 768,
                                                      p_wh + WP_OFF, 768*768/4);
        cvtw_kernel<<<(6144*768/4 + 255) / 256, 256>>>(fc1w + (size_t)d * 6144 * 768,
                                                       p_wh + WF1_OFF, 6144*768/4);
        cvtw_kernel<<<(768*3072/4 + 255) / 256, 256>>>(fc2w + (size_t)d * 768 * 3072,
                                                       p_wh + WF2_OFF, 768*3072/4);

        attn_kernel<<<512 * HEADS, 256, ATTN_SMEM>>>(shift);

        // proj: N=768, K=768
        gemm_mma<<<dim3(6, MTOK / 128), 128, SMEM_MMA>>>(
            p_aohi, p_aolo, p_wh + WP_OFF,
            projb + d * 768, p_proj, nullptr, nullptr, 768, 768, 0, -1);

        // x_mid = shortcut + LN(proj), un-window + un-roll scatter, emit fp16 hi/lo
        ln_kernel<<<MTOK / 8, 256>>>(p_proj, xin, n1g + d * 768, n1b + d * 768,
                                     p_xmid, p_xmhi, p_xmlo, shift);

        // FC1 gated-GELU: out cols 3072 (64/CTA), K=768, emits fp16 hi/lo
        gemm_mma<<<dim3(48, MTOK / 128), 128, SMEM_MMA>>>(
            p_xmhi, p_xmlo, p_wh + WF1_OFF,
            fc1b + (size_t)d * 2 * HID, nullptr, p_gahi, p_galo, 768, HID, 1, -1);

        // FC2: N=768, K=3072
        gemm_mma<<<dim3(6, MTOK / 128), 128, SMEM_MMA>>>(
            p_gahi, p_galo, p_wh + WF2_OFF,
            fc2b + d * 768, p_h2, nullptr, nullptr, 3072, 768, 0, -1);

        // final LN: block 0 -> x2 (+fp16 hi/lo reused as next layer's QKV A), block 1 -> out
        ln_kernel<<<MTOK / 8, 256>>>(p_h2, p_xmid, n2g + d * 768, n2b + d * 768,
                                     d == 0 ? p_x2 : out,
                                     d == 0 ? p_xhi : nullptr,
                                     d == 0 ? p_xlo : nullptr, -1);
    }
    (void)in_sizes; (void)n_in; (void)out_size;
}

// round 16
// speedup vs baseline: 1.2887x; 1.0011x over previous
#include <cuda_runtime.h>
#include <cuda_fp16.h>
#include <math.h>
#include <stdint.h>

#define BATCH 4
#define HRES  64
#define WRES  128
#define CDIM  768
#define HEADS 8
#define HDIM  96
#define WIN   8
#define NTOK  64
#define MTOK  32768
#define HID   3072

#define WQ_OFF  0
#define WP_OFF  1769472
#define WF1_OFF 2359296
#define WF2_OFF 7077888
#define WTOT    9437184

// ---------------- scratch ----------------
__device__ float g_qkv[(size_t)MTOK * 2304];
__device__ float g_proj[(size_t)MTOK * CDIM];
__device__ float g_xmid[(size_t)MTOK * CDIM];
__device__ float g_x2[(size_t)MTOK * CDIM];
__device__ float g_h2[(size_t)MTOK * CDIM];
__device__ float g_rpb[HEADS * NTOK * NTOK];
__device__ float g_scale[HEADS];
__device__ float g_qkvbias[2304];
// fp16 operand buffers: A-side 2-limb (hi/lo), weights 1-limb
__device__ __half g_xhi[(size_t)MTOK * CDIM],  g_xlo[(size_t)MTOK * CDIM];
__device__ __half g_aohi[(size_t)MTOK * CDIM], g_aolo[(size_t)MTOK * CDIM];
__device__ __half g_xmhi[(size_t)MTOK * CDIM], g_xmlo[(size_t)MTOK * CDIM];
__device__ __half g_gahi[(size_t)MTOK * HID],  g_galo[(size_t)MTOK * HID];
__device__ __half g_wh[WTOT];

// windowed row m -> image token index, applying roll by +shift
__device__ __forceinline__ int win2img(int m, int shift) {
    int w = m >> 6, tok = m & 63;
    int b = w >> 7, wi = w & 127;
    int y  = (((wi >> 4) << 3) + (tok >> 3) + shift) & 63;
    int xx = (((wi & 15) << 3) + (tok & 7) + shift) & 127;
    return (b << 13) + (y << 7) + xx;
}

__device__ __forceinline__ uint32_t smem_u32(const void* p) {
    uint32_t a;
    asm("{ .reg .u64 t; cvta.to.shared.u64 t, %1; cvt.u32.u64 %0, t; }" : "=r"(a) : "l"(p));
    return a;
}

__device__ __forceinline__ void split_f16(float v, unsigned short& h, unsigned short& l) {
    __half hh = __float2half_rn(v);
    h = __half_as_ushort(hh);
    l = __half_as_ushort(__float2half_rn(v - __half2float(hh)));
}

// ---------------- mma.sync / ldmatrix / cp.async helpers ----------------
__device__ __forceinline__ void mma_f16(float* c, const uint32_t* a, const uint32_t* b) {
    asm volatile(
        "mma.sync.aligned.m16n8k16.row.col.f32.f16.f16.f32 "
        "{%0,%1,%2,%3}, {%4,%5,%6,%7}, {%8,%9}, {%0,%1,%2,%3};"
        : "+f"(c[0]), "+f"(c[1]), "+f"(c[2]), "+f"(c[3])
        : "r"(a[0]), "r"(a[1]), "r"(a[2]), "r"(a[3]), "r"(b[0]), "r"(b[1]));
}
__device__ __forceinline__ void ldsm4(uint32_t* r, uint32_t addr) {
    asm volatile("ldmatrix.sync.aligned.m8n8.x4.shared.b16 {%0,%1,%2,%3}, [%4];"
                 : "=r"(r[0]), "=r"(r[1]), "=r"(r[2]), "=r"(r[3]) : "r"(addr));
}
#define CPA16(dst, src) asm volatile("cp.async.cg.shared.global [%0], [%1], 16;" :: "r"(dst), "l"(src) : "memory")
#define CPCOMMIT()      asm volatile("cp.async.commit_group;" ::: "memory")
#define CPWAIT1()       asm volatile("cp.async.wait_group 1;" ::: "memory")

// ---------------- fp32 -> fp16 hi/lo (A-side) ----------------
__global__ void cvt_kernel(const float* __restrict__ src, __half* __restrict__ hi,
                           __half* __restrict__ lo, int n4) {
    int i = blockIdx.x * 256 + threadIdx.x;
    if (i >= n4) return;
    float4 v = ((const float4*)src)[i];
    ushort4 h, l;
    split_f16(v.x, h.x, l.x);
    split_f16(v.y, h.y, l.y);
    split_f16(v.z, h.z, l.z);
    split_f16(v.w, h.w, l.w);
    ((ushort4*)hi)[i] = h;
    ((ushort4*)lo)[i] = l;
}

// ---------------- fp32 -> fp16 (weights, single limb) ----------------
__global__ void cvtw_kernel(const float* __restrict__ src, __half* __restrict__ hi, int n4) {
    int i = blockIdx.x * 256 + threadIdx.x;
    if (i >= n4) return;
    float4 v = ((const float4*)src)[i];
    ushort4 h;
    h.x = __half_as_ushort(__float2half_rn(v.x));
    h.y = __half_as_ushort(__float2half_rn(v.y));
    h.z = __half_as_ushort(__float2half_rn(v.z));
    h.w = __half_as_ushort(__float2half_rn(v.w));
    ((ushort4*)hi)[i] = h;
}

// ---------------- HMMA GEMM: C[m][n] = sum_k A[m][k]*W[n][k] + bias ----------------
// PROVEN R12/R15 CONFIG (UNCHANGED): CTA 128x128, BK=32, 2 stages, 2 CTAs/SM,
// 128 threads: 4 warps 2m x 2n, warp tile 64x64. fp16 2-limb A x 1-limb B.
#define STG 43008
#define SMEM_MMA (2 * STG)

__global__ __launch_bounds__(128, 2)
void gemm_mma(const __half* __restrict__ Ahi, const __half* __restrict__ Alo,
              const __half* __restrict__ Bh,
              const float* __restrict__ bias, float* __restrict__ Cout,
              __half* __restrict__ Chi, __half* __restrict__ Clo,
              int K, int Nout, int mode, int gatherShift) {
    extern __shared__ char sm[];
    uint32_t smb = smem_u32(sm);
    int tid = threadIdx.x, wid = tid >> 5, lane = tid & 31;
    int nB = blockIdx.x, mB = blockIdx.y;

    ptrdiff_t dA = Alo - Ahi;
    const __half* aSrc[4]; uint32_t aDst[4];
    #pragma unroll
    for (int i = 0; i < 4; i++) {
        int idx = tid + 128 * i, row = idx >> 2, ch = idx & 3;
        int m = mB * 128 + row;
        int rg = (gatherShift >= 0) ? win2img(m, gatherShift) : m;
        aSrc[i] = Ahi + (size_t)rg * K + ch * 8;
        aDst[i] = smb + row * 112 + ch * 16;
    }
    const __half* bSrc[4]; uint32_t bDst[4];
    #pragma unroll
    for (int i = 0; i < 4; i++) {
        int idx = tid + 128 * i, j = idx >> 2, ch = idx & 3;
        int grow = mode ? (nB * 64 + (j >> 1) + (j & 1) * HID) : (nB * 128 + j);
        bSrc[i] = Bh + (size_t)grow * K + ch * 8;
        bDst[i] = smb + 28672 + j * 112 + ch * 16;
    }

    #define PREFETCH(s, c) do {                                              \
        uint32_t so = (uint32_t)(s) * STG;                                   \
        _Pragma("unroll")                                                    \
        for (int i = 0; i < 4; i++) {                                        \
            const __half* sh = aSrc[i] + (c) * 32;                           \
            CPA16(aDst[i] + so, sh);                                         \
            CPA16(aDst[i] + so + 14336, sh + dA);                            \
        }                                                                    \
        _Pragma("unroll")                                                    \
        for (int i = 0; i < 4; i++) {                                        \
            CPA16(bDst[i] + so, bSrc[i] + (c) * 32);                         \
        }                                                                    \
    } while (0)

    int m0 = (wid & 1) * 64, n0 = (wid >> 1) * 64;
    uint32_t aoff = ((lane & 7) + ((lane >> 3) & 1) * 8) * 112 + ((lane >> 4) & 1) * 16;
    uint32_t boff = ((lane & 7) + ((lane >> 4) & 1) * 8) * 112 + ((lane >> 3) & 1) * 16;

    float acc[4][8][4];
    #pragma unroll
    for (int mt = 0; mt < 4; mt++)
        #pragma unroll
        for (int nt = 0; nt < 8; nt++)
            #pragma unroll
            for (int e = 0; e < 4; e++) acc[mt][nt][e] = 0.0f;

    int nchunk = K >> 5;
    PREFETCH(0, 0); CPCOMMIT();
    PREFETCH(1, 1); CPCOMMIT();

    for (int c = 0; c < nchunk; c++) {
        CPWAIT1();
        __syncthreads();
        int s = c & 1;
        uint32_t sa = smb + s * STG;
        uint32_t sb = sa + 28672;
        #pragma unroll
        for (int kk = 0; kk < 2; kk++) {
            uint32_t bh[4][4];
            #pragma unroll
            for (int bt = 0; bt < 4; bt++) {
                uint32_t bd = sb + (n0 + bt * 16) * 112 + kk * 32 + boff;
                ldsm4(bh[bt], bd);
            }
            #pragma unroll
            for (int mt = 0; mt < 4; mt++) {
                uint32_t ah[4], al[4];
                uint32_t ad = sa + (m0 + mt * 16) * 112 + kk * 32 + aoff;
                ldsm4(ah, ad);
                ldsm4(al, ad + 14336);
                #pragma unroll
                for (int nt = 0; nt < 8; nt++) {
                    float* cc = acc[mt][nt];
                    const uint32_t* bp = &bh[nt >> 1][(nt & 1) * 2];
                    mma_f16(cc, ah, bp);
                    mma_f16(cc, al, bp);
                }
            }
        }
        __syncthreads();
        if (c + 2 < nchunk) PREFETCH(s, c + 2);
        CPCOMMIT();
    }

    int g = lane >> 2, t = lane & 3;
    int rowBase = mB * 128 + m0;
    if (mode == 0) {
        int colBase = nB * 128 + n0;
        #pragma unroll
        for (int mt = 0; mt < 4; mt++)
            #pragma unroll
            for (int nt = 0; nt < 8; nt++) {
                float* a = acc[mt][nt];
                int row = rowBase + mt * 16 + g;
                int col = colBase + nt * 8 + 2 * t;
                float b0 = bias[col], b1 = bias[col + 1];
                float2 v0 = {a[0] + b0, a[1] + b1};
                float2 v1 = {a[2] + b0, a[3] + b1};
                *(float2*)&Cout[(size_t)row * Nout + col] = v0;
                *(float2*)&Cout[(size_t)(row + 8) * Nout + col] = v1;
            }
    } else {
        #pragma unroll
        for (int mt = 0; mt < 4; mt++)
            #pragma unroll
            for (int nt = 0; nt < 8; nt++) {
                float* a = acc[mt][nt];
                int row = rowBase + mt * 16 + g;
                int col = nB * 64 + ((n0 + nt * 8) >> 1) + t;
                float bg = bias[col], bv = bias[HID + col];
                float gt0 = a[0] + bg, vl0 = a[1] + bv;
                float gt1 = a[2] + bg, vl1 = a[3] + bv;
                float o0 = 0.5f * gt0 * (1.0f + erff(gt0 * 0.7071067811865475f)) * vl0;
                float o1 = 0.5f * gt1 * (1.0f + erff(gt1 * 0.7071067811865475f)) * vl1;
                unsigned short h0, l0, h1, l1;
                split_f16(o0, h0, l0);
                split_f16(o1, h1, l1);
                size_t i0 = (size_t)row * Nout + col;
                size_t i1 = (size_t)(row + 8) * Nout + col;
                Chi[i0] = __ushort_as_half(h0); Clo[i0] = __ushort_as_half(l0);
                Chi[i1] = __ushort_as_half(h1); Clo[i1] = __ushort_as_half(l1);
            }
    }
    #undef PREFETCH
}

// ---------------- CPB MLP + rpb table + scales + qkv bias ----------------
__device__ __forceinline__ float coordf(int i) {
    float t = (float)(i - 7) * (8.0f / 7.0f);
    return copysignf(log2f(fabsf(t) + 1.0f) * (1.0f / 3.0f), t);
}

__global__ void cpb_kernel(int d, const float* __restrict__ qb, const float* __restrict__ vb,
                           const float* __restrict__ ls, const float* __restrict__ w1,
                           const float* __restrict__ b1, const float* __restrict__ w2) {
    __shared__ float tbl[225][8];
    int tid = threadIdx.x;
    if (tid < 225) {
        int i = tid / 15, j = tid % 15;
        float c0 = coordf(i), c1 = coordf(j);
        float o[8] = {0,0,0,0,0,0,0,0};
        const float* W1 = w1 + d * 1024;
        const float* B1 = b1 + d * 512;
        const float* W2 = w2 + d * 4096;
        for (int u = 0; u < 512; u++) {
            float hv = fmaxf(c0 * W1[u*2] + c1 * W1[u*2+1] + B1[u], 0.0f);
            #pragma unroll
            for (int hh = 0; hh < 8; hh++) o[hh] += hv * W2[hh*512 + u];
        }
        #pragma unroll
        for (int hh = 0; hh < 8; hh++) tbl[tid][hh] = o[hh];
    }
    if (tid < 8) g_scale[tid] = __expf(fminf(ls[d*8 + tid], 4.605170185988091f));
    for (int n = tid; n < 2304; n += 256) {
        float bb = 0.0f;
        if (n < 768) bb = qb[d*768 + n];
        else if (n >= 1536) bb = vb[d*768 + n - 1536];
        g_qkvbias[n] = bb;
    }
    __syncthreads();
    for (int idx = tid; idx < HEADS*NTOK*NTOK; idx += 256) {
        int h = idx >> 12, rem = idx & 4095;
        int i = rem >> 6, j = rem & 63;
        int dy = (i >> 3) - (j >> 3) + 7;
        int dx = (i & 7) - (j & 7) + 7;
        float t = tbl[dy*15 + dx][h];
        g_rpb[idx] = 16.0f / (1.0f + __expf(-t));
    }
}

// ---------------- attention: one CTA per (window, head) ----------------
#define QS_LD 97
#define AT_LD 65
#define ATTN_SMEM ((3 * 64 * QS_LD + 64 * AT_LD) * (int)sizeof(float))

__global__ __launch_bounds__(256)
void attn_kernel(int shift) {
    extern __shared__ float smf[];
    float* Qs = smf;
    float* Ks = Qs + 64 * QS_LD;
    float* Vs = Ks + 64 * QS_LD;
    float* At = Vs + 64 * QS_LD;
    int wh = blockIdx.x;
    int w = wh >> 3, h = wh & 7;
    int tid = threadIdx.x;

    #pragma unroll
    for (int s = 0; s < 3; s++) {
        float* dst = (s == 0) ? Qs : ((s == 1) ? Ks : Vs);
        for (int idx = tid; idx < 64 * 24; idx += 256) {
            int row = idx / 24, c4 = idx % 24;
            float4 v = *(const float4*)&g_qkv[(size_t)(w * 64 + row) * 2304 + s * 768 + h * 96 + c4 * 4];
            float* p = dst + row * QS_LD + c4 * 4;
            p[0] = v.x; p[1] = v.y; p[2] = v.z; p[3] = v.w;
        }
    }
    __syncthreads();

    // cosine normalization: all 256 threads, 2 threads per row (48 cols each)
    {
        int r = tid >> 1, half = tid & 1;
        float* rowp = (r < 64) ? (Qs + r * QS_LD) : (Ks + (r - 64) * QS_LD);
        int c0 = half * 48;
        float ss = 0.0f;
        #pragma unroll 8
        for (int c = 0; c < 48; c++) { float vv = rowp[c0 + c]; ss += vv * vv; }
        ss += __shfl_xor_sync(0xffffffffu, ss, 1);
        float f = 1.0f / fmaxf(sqrtf(ss), 1e-12f);
        if (r < 64) f *= g_scale[h];
        #pragma unroll 8
        for (int c = 0; c < 48; c++) rowp[c0 + c] *= f;
    }
    __syncthreads();

    int ty = tid >> 4, tx = tid & 15;
    int i0 = ty * 4, j0 = tx * 4;
    float acc[4][4];
    #pragma unroll
    for (int r = 0; r < 4; r++)
        #pragma unroll
        for (int c = 0; c < 4; c++) acc[r][c] = 0.0f;
    for (int dd = 0; dd < 96; dd++) {
        float q[4], k[4];
        #pragma unroll
        for (int r = 0; r < 4; r++) q[r] = Qs[(i0 + r) * QS_LD + dd];
        #pragma unroll
        for (int c = 0; c < 4; c++) k[c] = Ks[(j0 + c) * QS_LD + dd];
        #pragma unroll
        for (int r = 0; r < 4; r++)
            #pragma unroll
            for (int c = 0; c < 4; c++) acc[r][c] += q[r] * k[c];
    }
    int wi = w & 127;
    int wy = wi >> 4, wx = wi & 15;
    #pragma unroll
    for (int r = 0; r < 4; r++) {
        #pragma unroll
        for (int c = 0; c < 4; c++) {
            int i = i0 + r, j = j0 + c;
            float aval = acc[r][c] + g_rpb[h * 4096 + i * 64 + j];
            if (shift > 0) {
                int yi = wy * 8 + (i >> 3), xi = wx * 8 + (i & 7);
                int yj = wy * 8 + (j >> 3), xj = wx * 8 + (j & 7);
                int ri = (yi >= 60 ? 2 : (yi >= 56 ? 1 : 0)) * 3 + (xi >= 124 ? 2 : (xi >= 120 ? 1 : 0));
                int rj = (yj >= 60 ? 2 : (yj >= 56 ? 1 : 0)) * 3 + (xj >= 124 ? 2 : (xj >= 120 ? 1 : 0));
                if (ri != rj) aval -= 100.0f;
            }
            At[i * AT_LD + j] = aval;
        }
    }
    __syncthreads();

    {
        int r = tid >> 2, qd = tid & 3;
        int jb = qd * 16;
        float mx = -1e30f;
        #pragma unroll
        for (int j = 0; j < 16; j++) mx = fmaxf(mx, At[r * AT_LD + jb + j]);
        mx = fmaxf(mx, __shfl_xor_sync(0xffffffffu, mx, 1));
        mx = fmaxf(mx, __shfl_xor_sync(0xffffffffu, mx, 2));
        float s = 0.0f;
        #pragma unroll
        for (int j = 0; j < 16; j++) {
            float e = __expf(At[r * AT_LD + jb + j] - mx);
            At[r * AT_LD + jb + j] = e;
            s += e;
        }
        s += __shfl_xor_sync(0xffffffffu, s, 1);
        s += __shfl_xor_sync(0xffffffffu, s, 2);
        float inv = 1.0f / s;
        #pragma unroll
        for (int j = 0; j < 16; j++) At[r * AT_LD + jb + j] *= inv;
    }
    __syncthreads();

    int d0 = tx * 6;
    float o[4][6];
    #pragma unroll
    for (int r = 0; r < 4; r++)
        #pragma unroll
        for (int c = 0; c < 6; c++) o[r][c] = 0.0f;
    for (int j = 0; j < 64; j++) {
        float a[4], vv[6];
        #pragma unroll
        for (int r = 0; r < 4; r++) a[r] = At[(i0 + r) * AT_LD + j];
        #pragma unroll
        for (int c = 0; c < 6; c++) vv[c] = Vs[j * QS_LD + d0 + c];
        #pragma unroll
        for (int r = 0; r < 4; r++)
            #pragma unroll
            for (int c = 0; c < 6; c++) o[r][c] += a[r] * vv[c];
    }
    #pragma unroll
    for (int r = 0; r < 4; r++)
        #pragma unroll
        for (int c = 0; c < 6; c++) {
            size_t idx = (size_t)(w * 64 + i0 + r) * 768 + h * 96 + d0 + c;
            unsigned short hh, ll;
            split_f16(o[r][c], hh, ll);
            g_aohi[idx] = __ushort_as_half(hh);
            g_aolo[idx] = __ushort_as_half(ll);
        }
}

// ---------------- LayerNorm + residual, float4-vectorized ----------------
__global__ void ln_kernel(const float* __restrict__ src, const float* __restrict__ resid,
                          const float* __restrict__ gamma, const float* __restrict__ beta,
                          float* __restrict__ outp,
                          __half* __restrict__ ohi, __half* __restrict__ olo,
                          int scatterShift) {
    int warp = threadIdx.x >> 5, lane = threadIdx.x & 31;
    int m = blockIdx.x * 8 + warp;
    const float4* sp4 = (const float4*)(src + (size_t)m * 768);
    float4 v[6];
    #pragma unroll
    for (int i = 0; i < 6; i++) v[i] = sp4[i * 32 + lane];
    float s = 0.0f;
    #pragma unroll
    for (int i = 0; i < 6; i++) s += v[i].x + v[i].y + v[i].z + v[i].w;
    #pragma unroll
    for (int o = 16; o; o >>= 1) s += __shfl_xor_sync(0xffffffffu, s, o);
    float mu = s * (1.0f / 768.0f);
    float q = 0.0f;
    #pragma unroll
    for (int i = 0; i < 6; i++) {
        float d0 = v[i].x - mu, d1 = v[i].y - mu, d2 = v[i].z - mu, d3 = v[i].w - mu;
        q += d0 * d0 + d1 * d1 + d2 * d2 + d3 * d3;
    }
    #pragma unroll
    for (int o = 16; o; o >>= 1) q += __shfl_xor_sync(0xffffffffu, q, o);
    float rs = rsqrtf(q * (1.0f / 768.0f) + 1e-5f);
    int timg = (scatterShift >= 0) ? win2img(m, scatterShift) : m;
    size_t ob = (size_t)timg * 768;
    const float4* rp4 = (const float4*)(resid + ob);
    const float4* gp4 = (const float4*)gamma;
    const float4* bp4 = (const float4*)beta;
    float4* op4 = (float4*)(outp + ob);
    #pragma unroll
    for (int i = 0; i < 6; i++) {
        int f = i * 32 + lane;
        float4 rv = rp4[f], gv = gp4[f], bv = bp4[f];
        float4 ov;
        ov.x = rv.x + (v[i].x - mu) * rs * gv.x + bv.x;
        ov.y = rv.y + (v[i].y - mu) * rs * gv.y + bv.y;
        ov.z = rv.z + (v[i].z - mu) * rs * gv.z + bv.z;
        ov.w = rv.w + (v[i].w - mu) * rs * gv.w + bv.w;
        op4[f] = ov;
        if (ohi != nullptr) {
            ushort4 hh, ll;
            split_f16(ov.x, hh.x, ll.x);
            split_f16(ov.y, hh.y, ll.y);
            split_f16(ov.z, hh.z, ll.z);
            split_f16(ov.w, hh.w, ll.w);
            *(ushort4*)(ohi + ob + 4 * f) = hh;
            *(ushort4*)(olo + ob + 4 * f) = ll;
        }
    }
}

// ---------------- driver ----------------
extern "C" void kernel_launch(void* const* d_in, const int* in_sizes, int n_in,
                              void* d_out, int out_size) {
    const float* x     = (const float*)d_in[0];
    const float* n1g   = (const float*)d_in[1];
    const float* n1b   = (const float*)d_in[2];
    const float* n2g   = (const float*)d_in[3];
    const float* n2b   = (const float*)d_in[4];
    const float* qkvw  = (const float*)d_in[5];
    const float* qb    = (const float*)d_in[6];
    const float* vb    = (const float*)d_in[7];
    const float* ls    = (const float*)d_in[8];
    const float* w1    = (const float*)d_in[9];
    const float* b1    = (const float*)d_in[10];
    const float* w2    = (const float*)d_in[11];
    const float* projw = (const float*)d_in[12];
    const float* projb = (const float*)d_in[13];
    const float* fc1w  = (const float*)d_in[14];
    const float* fc1b  = (const float*)d_in[15];
    const float* fc2w  = (const float*)d_in[16];
    const float* fc2b  = (const float*)d_in[17];
    float* out = (float*)d_out;

    float *p_qkv, *p_proj, *p_xmid, *p_x2, *p_h2, *p_qkvbias;
    __half *p_xhi, *p_xlo, *p_aohi, *p_aolo, *p_xmhi, *p_xmlo, *p_gahi, *p_galo, *p_wh;
    cudaGetSymbolAddress((void**)&p_qkv, g_qkv);
    cudaGetSymbolAddress((void**)&p_proj, g_proj);
    cudaGetSymbolAddress((void**)&p_xmid, g_xmid);
    cudaGetSymbolAddress((void**)&p_x2, g_x2);
    cudaGetSymbolAddress((void**)&p_h2, g_h2);
    cudaGetSymbolAddress((void**)&p_qkvbias, g_qkvbias);
    cudaGetSymbolAddress((void**)&p_xhi, g_xhi);
    cudaGetSymbolAddress((void**)&p_xlo, g_xlo);
    cudaGetSymbolAddress((void**)&p_aohi, g_aohi);
    cudaGetSymbolAddress((void**)&p_aolo, g_aolo);
    cudaGetSymbolAddress((void**)&p_xmhi, g_xmhi);
    cudaGetSymbolAddress((void**)&p_xmlo, g_xmlo);
    cudaGetSymbolAddress((void**)&p_gahi, g_gahi);
    cudaGetSymbolAddress((void**)&p_galo, g_galo);
    cudaGetSymbolAddress((void**)&p_wh, g_wh);

    cudaFuncSetAttribute(attn_kernel, cudaFuncAttributeMaxDynamicSharedMemorySize, ATTN_SMEM);
    cudaFuncSetAttribute(gemm_mma, cudaFuncAttributeMaxDynamicSharedMemorySize, SMEM_MMA);

    for (int d = 0; d < 2; d++) {
        int shift = d ? 4 : 0;
        const float* xin = d ? p_x2 : x;

        cpb_kernel<<<1, 256>>>(d, qb, vb, ls, w1, b1, w2);

        if (d == 0)
            cvt_kernel<<<(MTOK * CDIM / 4 + 255) / 256, 256>>>(x, p_xhi, p_xlo, MTOK * CDIM / 4);
        cvtw_kernel<<<(2304*768/4 + 255) / 256, 256>>>(qkvw + (size_t)d * 2304 * 768,
                                                       p_wh + WQ_OFF, 2304*768/4);

        // QKV (fused roll+window gather on A): M=32768, N=2304, K=768
        gemm_mma<<<dim3(18, MTOK / 128), 128, SMEM_MMA>>>(
            p_xhi, p_xlo, p_wh + WQ_OFF,
            p_qkvbias, p_qkv, nullptr, nullptr, 768, 2304, 0, shift);

        // weight conversions for later GEMMs (deferred past the QKV launch)
        cvtw_kernel<<<(768*768/4 + 255) / 256, 256>>>(projw + (size_t)d * 768 * 768,
                                                      p_wh + WP_OFF, 768*768/4);
        cvtw_kernel<<<(6144*768/4 + 255) / 256, 256>>>(fc1w + (size_t)d * 6144 * 768,
                                                       p_wh + WF1_OFF, 6144*768/4);
        cvtw_kernel<<<(768*3072/4 + 255) / 256, 256>>>(fc2w + (size_t)d * 768 * 3072,
                                                       p_wh + WF2_OFF, 768*3072/4);

        attn_kernel<<<512 * HEADS, 256, ATTN_SMEM>>>(shift);

        // proj: N=768, K=768
        gemm_mma<<<dim3(6, MTOK / 128), 128, SMEM_MMA>>>(
            p_aohi, p_aolo, p_wh + WP_OFF,
            projb + d * 768, p_proj, nullptr, nullptr, 768, 768, 0, -1);

        // x_mid = shortcut + LN(proj), un-window + un-roll scatter, emit fp16 hi/lo
        ln_kernel<<<MTOK / 8, 256>>>(p_proj, xin, n1g + d * 768, n1b + d * 768,
                                     p_xmid, p_xmhi, p_xmlo, shift);

        // FC1 gated-GELU: out cols 3072 (64/CTA), K=768, emits fp16 hi/lo
        gemm_mma<<<dim3(48, MTOK / 128), 128, SMEM_MMA>>>(
            p_xmhi, p_xmlo, p_wh + WF1_OFF,
            fc1b + (size_t)d * 2 * HID, nullptr, p_gahi, p_galo, 768, HID, 1, -1);

        // FC2: N=768, K=3072
        gemm_mma<<<dim3(6, MTOK / 128), 128, SMEM_MMA>>>(
            p_gahi, p_galo, p_wh + WF2_OFF,
            fc2b + d * 768, p_h2, nullptr, nullptr, 3072, 768, 0, -1);

        // final LN: block 0 -> x2 (+fp16 hi/lo reused as next layer's QKV A), block 1 -> out
        ln_kernel<<<MTOK / 8, 256>>>(p_h2, p_xmid, n2g + d * 768, n2b + d * 768,
                                     d == 0 ? p_x2 : out,
                                     d == 0 ? p_xhi : nullptr,
                                     d == 0 ? p_xlo : nullptr, -1);
    }
    (void)in_sizes; (void)n_in; (void)out_size;
}